// round 2
// baseline (speedup 1.0000x reference)
#include <cuda_runtime.h>

#define NV 1497600          // 256 * 5850
#define NE 4492800          // 3 * NV
#define NB 256
#define VPM 5850
#define KDIM 58500          // VPM * 10
#define NEG 0.01f

// ---------------- scratch (static device memory; no allocs) ----------------
__device__ float g_xA[(size_t)NV * 8];    // layer-A accumulator, padded 5->8
__device__ float g_nA[(size_t)NV * 8];    // layer-A neighbor features
__device__ float g_xB[(size_t)NV * 20];   // layer-B accumulator
__device__ float g_nB[(size_t)NV * 20];   // layer-B neighbor features
__device__ float g_y [(size_t)NV * 10];   // fc1 output == flat (256, 58500)
__device__ float g_logits[NB * 64];

__device__ __forceinline__ float leaky(float t) { return t >= 0.f ? t : NEG * t; }

__device__ __forceinline__ void red4(float* p, float4 v) {
    asm volatile("red.global.add.v4.f32 [%0], {%1,%2,%3,%4};"
                 :: "l"(p), "f"(v.x), "f"(v.y), "f"(v.z), "f"(v.w) : "memory");
}
__device__ __forceinline__ void red1(float* p, float v) {
    asm volatile("red.global.add.f32 [%0], %1;" :: "l"(p), "f"(v) : "memory");
}

// ---------------- K1: verts -> (outA, nbrA), 3->5 both -----------------
__global__ void k1_lin_a(const float* __restrict__ verts,
                         const float* __restrict__ w0, const float* __restrict__ b0,
                         const float* __restrict__ w1, const float* __restrict__ b1) {
    int v = blockIdx.x * blockDim.x + threadIdx.x;
    if (v >= NV) return;
    float p0 = verts[(size_t)v*3+0], p1 = verts[(size_t)v*3+1], p2 = verts[(size_t)v*3+2];
    float o[5], n[5];
#pragma unroll
    for (int c = 0; c < 5; c++) {
        o[c] = fmaf(w0[c*3+0], p0, fmaf(w0[c*3+1], p1, fmaf(w0[c*3+2], p2, b0[c])));
        n[c] = fmaf(w1[c*3+0], p0, fmaf(w1[c*3+1], p1, fmaf(w1[c*3+2], p2, b1[c])));
    }
    *(float4*)&g_xA[(size_t)v*8] = make_float4(o[0], o[1], o[2], o[3]);
    g_xA[(size_t)v*8+4] = o[4];
    *(float4*)&g_nA[(size_t)v*8] = make_float4(n[0], n[1], n[2], n[3]);
    g_nA[(size_t)v*8+4] = n[4];
}

// ---------------- K2: scatter layer A ----------------
__global__ void k2_scatter_a(const int* __restrict__ edges) {
    int e = blockIdx.x * blockDim.x + threadIdx.x;
    if (e >= NE) return;
    int2 ij = ((const int2*)edges)[e];
    size_t oi = (size_t)ij.x * 8, oj = (size_t)ij.y * 8;
    float4 a  = *(const float4*)&g_nA[oj];
    float  a4 = g_nA[oj + 4];
    float4 b  = *(const float4*)&g_nA[oi];
    float  b4 = g_nA[oi + 4];
    red4(&g_xA[oi], a);  red1(&g_xA[oi + 4], a4);
    red4(&g_xA[oj], b);  red1(&g_xA[oj + 4], b4);
}

// ---------------- K3: leaky(xA) -> (outB, nbrB), 5->20 both ----------------
__global__ void k3_lin_b(const float* __restrict__ w0, const float* __restrict__ b0,
                         const float* __restrict__ w1, const float* __restrict__ b1) {
    __shared__ float sw0[100], sw1[100], sb0[20], sb1[20];
    int t = threadIdx.x;
    if (t < 100) { sw0[t] = w0[t]; sw1[t] = w1[t]; }
    if (t < 20)  { sb0[t] = b0[t]; sb1[t] = b1[t]; }
    __syncthreads();
    int v = blockIdx.x * blockDim.x + t;
    if (v >= NV) return;
    float4 q = *(const float4*)&g_xA[(size_t)v*8];
    float x[5];
    x[0] = leaky(q.x); x[1] = leaky(q.y); x[2] = leaky(q.z); x[3] = leaky(q.w);
    x[4] = leaky(g_xA[(size_t)v*8 + 4]);
#pragma unroll
    for (int n = 0; n < 20; n += 4) {
        float4 o, m;
        float* op = (float*)&o; float* mp = (float*)&m;
#pragma unroll
        for (int u = 0; u < 4; u++) {
            float ao = sb0[n+u], am = sb1[n+u];
#pragma unroll
            for (int c = 0; c < 5; c++) {
                ao = fmaf(x[c], sw0[(n+u)*5 + c], ao);
                am = fmaf(x[c], sw1[(n+u)*5 + c], am);
            }
            op[u] = ao; mp[u] = am;
        }
        *(float4*)&g_xB[(size_t)v*20 + n] = o;
        *(float4*)&g_nB[(size_t)v*20 + n] = m;
    }
}

// ---------------- K4: scatter layer B ----------------
__global__ void k4_scatter_b(const int* __restrict__ edges) {
    int e = blockIdx.x * blockDim.x + threadIdx.x;
    if (e >= NE) return;
    int2 ij = ((const int2*)edges)[e];
    size_t oi = (size_t)ij.x * 20, oj = (size_t)ij.y * 20;
#pragma unroll
    for (int c = 0; c < 20; c += 4) {
        float4 a = *(const float4*)&g_nB[oj + c];
        red4(&g_xB[oi + c], a);
    }
#pragma unroll
    for (int c = 0; c < 20; c += 4) {
        float4 b = *(const float4*)&g_nB[oi + c];
        red4(&g_xB[oj + c], b);
    }
}

// ---------------- K5: leaky(xB) -> fc1 -> leaky -> y (20->10) ----------------
__global__ void k5_fc1(const float* __restrict__ fw, const float* __restrict__ fb) {
    __shared__ float sw[200], sb[10];
    int t = threadIdx.x;
    if (t < 200) sw[t] = fw[t];
    if (t < 10)  sb[t] = fb[t];
    __syncthreads();
    int v = blockIdx.x * blockDim.x + t;
    if (v >= NV) return;
    float x[20];
#pragma unroll
    for (int c = 0; c < 20; c += 4) {
        float4 q = *(const float4*)&g_xB[(size_t)v*20 + c];
        x[c+0] = leaky(q.x); x[c+1] = leaky(q.y);
        x[c+2] = leaky(q.z); x[c+3] = leaky(q.w);
    }
    float h[10];
#pragma unroll
    for (int n = 0; n < 10; n++) {
        float a = sb[n];
#pragma unroll
        for (int c = 0; c < 20; c++) a = fmaf(x[c], sw[n*20 + c], a);
        h[n] = leaky(a);
    }
#pragma unroll
    for (int n = 0; n < 10; n += 2)
        *(float2*)&g_y[(size_t)v*10 + n] = make_float2(h[n], h[n+1]);
}

// ---------------- K6a: zero logits ----------------
__global__ void k6_zero() {
    int i = blockIdx.x * blockDim.x + threadIdx.x;
    if (i < NB * 64) g_logits[i] = 0.f;
}

// ---------------- K6b: split-K GEMM  logits += Y(256xK) @ W^T(Kx64) ----------------
#define BM 64
#define BK 32
#define KSPLIT 256
__global__ void k6_gemm(const float* __restrict__ w) {
    __shared__ float Ys[BM][BK + 1];
    __shared__ float Ws[64][BK + 1];
    int t = threadIdx.x;                 // 256 threads
    int m0 = blockIdx.x * BM;            // 4 m-tiles
    int kbase = blockIdx.y * KSPLIT;     // 229 k-splits
    int tr = t >> 4;                     // 0..15 (m sub-index)
    int tc = t & 15;                     // 0..15 (n sub-index)
    float acc[4][4] = {};
    for (int kk = 0; kk < KSPLIT; kk += BK) {
#pragma unroll
        for (int r = 0; r < 2; r++) {
            int idx = t + r * 256;             // 0..511 float4 slots
            int row = idx >> 3;                // 0..63
            int kc  = (idx & 7) * 4;
            int kg  = kbase + kk + kc;
            float4 yv = make_float4(0.f, 0.f, 0.f, 0.f);
            float4 wv = make_float4(0.f, 0.f, 0.f, 0.f);
            if (kg < KDIM) {
                yv = *(const float4*)&g_y[(size_t)(m0 + row) * KDIM + kg];
                wv = *(const float4*)&w[(size_t)row * KDIM + kg];
            }
            Ys[row][kc+0] = yv.x; Ys[row][kc+1] = yv.y;
            Ys[row][kc+2] = yv.z; Ys[row][kc+3] = yv.w;
            Ws[row][kc+0] = wv.x; Ws[row][kc+1] = wv.y;
            Ws[row][kc+2] = wv.z; Ws[row][kc+3] = wv.w;
        }
        __syncthreads();
#pragma unroll 8
        for (int k2 = 0; k2 < BK; k2++) {
            float ya[4], wa[4];
#pragma unroll
            for (int u = 0; u < 4; u++) ya[u] = Ys[tr + 16*u][k2];
#pragma unroll
            for (int u = 0; u < 4; u++) wa[u] = Ws[tc + 16*u][k2];
#pragma unroll
            for (int um = 0; um < 4; um++)
#pragma unroll
                for (int un = 0; un < 4; un++)
                    acc[um][un] = fmaf(ya[um], wa[un], acc[um][un]);
        }
        __syncthreads();
    }
#pragma unroll
    for (int um = 0; um < 4; um++)
#pragma unroll
        for (int un = 0; un < 4; un++)
            atomicAdd(&g_logits[(m0 + tr + 16*um) * 64 + (tc + 16*un)], acc[um][un]);
}

// ---------------- K7: bias + softmax(64) ----------------
__global__ void k7_softmax(const float* __restrict__ fb, float* __restrict__ out) {
    int b = blockIdx.x;
    int t = threadIdx.x;   // 64 threads
    float v = g_logits[b * 64 + t] + fb[t];
    __shared__ float r0[2], r1[2];
    float m = v;
#pragma unroll
    for (int o = 16; o; o >>= 1) m = fmaxf(m, __shfl_xor_sync(0xffffffffu, m, o));
    if ((t & 31) == 0) r0[t >> 5] = m;
    __syncthreads();
    m = fmaxf(r0[0], r0[1]);
    float e = expf(v - m);
    float s = e;
#pragma unroll
    for (int o = 16; o; o >>= 1) s += __shfl_xor_sync(0xffffffffu, s, o);
    if ((t & 31) == 0) r1[t >> 5] = s;
    __syncthreads();
    s = r1[0] + r1[1];
    out[b * 64 + t] = e / s;
}

// ---------------- launch ----------------
extern "C" void kernel_launch(void* const* d_in, const int* in_sizes, int n_in,
                              void* d_out, int out_size) {
    const float* verts = (const float*)d_in[0];
    const int*   edges = (const int*)  d_in[1];
    const float* w0a = (const float*)d_in[2];  const float* b0a = (const float*)d_in[3];
    const float* w1a = (const float*)d_in[4];  const float* b1a = (const float*)d_in[5];
    const float* w0b = (const float*)d_in[6];  const float* b0b = (const float*)d_in[7];
    const float* w1b = (const float*)d_in[8];  const float* b1b = (const float*)d_in[9];
    const float* f1w = (const float*)d_in[10]; const float* f1b = (const float*)d_in[11];
    const float* f2w = (const float*)d_in[12]; const float* f2b = (const float*)d_in[13];
    float* out = (float*)d_out;

    k1_lin_a   <<<(NV + 255) / 256, 256>>>(verts, w0a, b0a, w1a, b1a);
    k2_scatter_a<<<(NE + 255) / 256, 256>>>(edges);
    k3_lin_b   <<<(NV + 255) / 256, 256>>>(w0b, b0b, w1b, b1b);
    k4_scatter_b<<<(NE + 255) / 256, 256>>>(edges);
    k5_fc1     <<<(NV + 255) / 256, 256>>>(f1w, f1b);
    k6_zero    <<<64, 256>>>();
    dim3 g6(256 / BM, (KDIM + KSPLIT - 1) / KSPLIT);   // (4, 229)
    k6_gemm    <<<g6, 256>>>(f2w);
    k7_softmax <<<NB, 64>>>(f2b, out);
}

// round 6
// speedup vs baseline: 2.7692x; 2.7692x over previous
#include <cuda_runtime.h>

#define NV 1497600          // 256 * 5850
#define NE 4492800          // 3 * NV
#define NB 256
#define VPM 5850
#define KDIM 58500          // VPM * 10
#define NEG 0.01f

// ---------------- scratch (static device memory; no allocs) ----------------
__device__ float g_p4[(size_t)NV * 4];    // (vx, vy, vz, 1)
__device__ float g_s1[(size_t)NV * 4];    // pass-1 scatter acc: sum nbr p4 (w = degree)
__device__ float g_q8[(size_t)NV * 8];    // leaky(xA), 5 used, padded 8
__device__ float g_s2[(size_t)NV * 8];    // pass-2 scatter acc: sum nbr q
__device__ float g_y [(size_t)NV * 10];   // fc1 output == flat (256, 58500)
__device__ float g_logits[NB * 64];

__device__ __forceinline__ float leaky(float t) { return t >= 0.f ? t : NEG * t; }

__device__ __forceinline__ void red4(float* p, float4 v) {
    asm volatile("red.global.add.v4.f32 [%0], {%1,%2,%3,%4};"
                 :: "l"(p), "f"(v.x), "f"(v.y), "f"(v.z), "f"(v.w) : "memory");
}
__device__ __forceinline__ void red1(float* p, float v) {
    asm volatile("red.global.add.f32 [%0], %1;" :: "l"(p), "f"(v) : "memory");
}

// ---------------- K1: pack verts -> p4, zero s1 ----------------
__global__ void k1_pack(const float* __restrict__ verts) {
    int v = blockIdx.x * blockDim.x + threadIdx.x;
    if (v >= NV) return;
    float p0 = verts[(size_t)v*3+0], p1 = verts[(size_t)v*3+1], p2 = verts[(size_t)v*3+2];
    *(float4*)&g_p4[(size_t)v*4] = make_float4(p0, p1, p2, 1.0f);
    *(float4*)&g_s1[(size_t)v*4] = make_float4(0.f, 0.f, 0.f, 0.f);
}

// ---------------- K2: pass-1 scatter (raw verts + degree) ----------------
__global__ void k2_scatter1(const int* __restrict__ edges) {
    int e = blockIdx.x * blockDim.x + threadIdx.x;
    if (e >= NE) return;
    int2 ij = ((const int2*)edges)[e];
    float4 a = *(const float4*)&g_p4[(size_t)ij.y * 4];
    float4 b = *(const float4*)&g_p4[(size_t)ij.x * 4];
    red4(&g_s1[(size_t)ij.x * 4], a);
    red4(&g_s1[(size_t)ij.y * 4], b);
}

// ---------------- K3: xA = leaky(p@w0a + b0a + s1.xyz@w1a + deg*b1a); zero s2 ----
__global__ void k3_lin_a(const float* __restrict__ w0, const float* __restrict__ b0,
                         const float* __restrict__ w1, const float* __restrict__ b1) {
    __shared__ float sw0[15], sw1[15], sb0[5], sb1[5];
    int t = threadIdx.x;
    if (t < 15) { sw0[t] = w0[t]; sw1[t] = w1[t]; }
    if (t < 5)  { sb0[t] = b0[t]; sb1[t] = b1[t]; }
    __syncthreads();
    int v = blockIdx.x * blockDim.x + t;
    if (v >= NV) return;
    float4 p = *(const float4*)&g_p4[(size_t)v*4];
    float4 s = *(const float4*)&g_s1[(size_t)v*4];
    float x[5];
#pragma unroll
    for (int c = 0; c < 5; c++) {
        float a = fmaf(sw0[c*3+0], p.x, fmaf(sw0[c*3+1], p.y, fmaf(sw0[c*3+2], p.z, sb0[c])));
        a = fmaf(sw1[c*3+0], s.x, fmaf(sw1[c*3+1], s.y, fmaf(sw1[c*3+2], s.z, a)));
        a = fmaf(s.w, sb1[c], a);
        x[c] = leaky(a);
    }
    *(float4*)&g_q8[(size_t)v*8]     = make_float4(x[0], x[1], x[2], x[3]);
    *(float4*)&g_q8[(size_t)v*8 + 4] = make_float4(x[4], 0.f, 0.f, 0.f);
    *(float4*)&g_s2[(size_t)v*8]     = make_float4(0.f, 0.f, 0.f, 0.f);
    *(float4*)&g_s2[(size_t)v*8 + 4] = make_float4(0.f, 0.f, 0.f, 0.f);
}

// ---------------- K4: pass-2 scatter (5-float leaky(xA)) ----------------
__global__ void k4_scatter2(const int* __restrict__ edges) {
    int e = blockIdx.x * blockDim.x + threadIdx.x;
    if (e >= NE) return;
    int2 ij = ((const int2*)edges)[e];
    size_t oi = (size_t)ij.x * 8, oj = (size_t)ij.y * 8;
    float4 a  = *(const float4*)&g_q8[oj];
    float  a4 = g_q8[oj + 4];
    float4 b  = *(const float4*)&g_q8[oi];
    float  b4 = g_q8[oi + 4];
    red4(&g_s2[oi], a);  red1(&g_s2[oi + 4], a4);
    red4(&g_s2[oj], b);  red1(&g_s2[oj + 4], b4);
}

// ---- K5: xB = leaky(x@w0b + b0b + s2@w1b + deg*b1b); y = leaky(xB@fc1 + fc1b) ----
__global__ void k5_fused(const float* __restrict__ w0, const float* __restrict__ b0,
                         const float* __restrict__ w1, const float* __restrict__ b1,
                         const float* __restrict__ fw, const float* __restrict__ fb) {
    __shared__ float sw0[100], sw1[100], sb0[20], sb1[20], sfw[200], sfb[10];
    int t = threadIdx.x;
    if (t < 100) { sw0[t] = w0[t]; sw1[t] = w1[t]; }
    if (t < 20)  { sb0[t] = b0[t]; sb1[t] = b1[t]; }
    if (t < 200) sfw[t] = fw[t];
    if (t < 10)  sfb[t] = fb[t];
    __syncthreads();
    int v = blockIdx.x * blockDim.x + t;
    if (v >= NV) return;
    float4 xq = *(const float4*)&g_q8[(size_t)v*8];
    float  x4 = g_q8[(size_t)v*8 + 4];
    float4 sq = *(const float4*)&g_s2[(size_t)v*8];
    float  s4 = g_s2[(size_t)v*8 + 4];
    float  deg = g_s1[(size_t)v*4 + 3];
    float x[5] = {xq.x, xq.y, xq.z, xq.w, x4};
    float s[5] = {sq.x, sq.y, sq.z, sq.w, s4};
    float xb[20];
#pragma unroll
    for (int n = 0; n < 20; n++) {
        float a = fmaf(deg, sb1[n], sb0[n]);
#pragma unroll
        for (int c = 0; c < 5; c++) {
            a = fmaf(x[c], sw0[n*5 + c], a);
            a = fmaf(s[c], sw1[n*5 + c], a);
        }
        xb[n] = leaky(a);
    }
    float h[10];
#pragma unroll
    for (int n = 0; n < 10; n++) {
        float a = sfb[n];
#pragma unroll
        for (int c = 0; c < 20; c++) a = fmaf(xb[c], sfw[n*20 + c], a);
        h[n] = leaky(a);
    }
#pragma unroll
    for (int n = 0; n < 10; n += 2)
        *(float2*)&g_y[(size_t)v*10 + n] = make_float2(h[n], h[n+1]);
}

// ---------------- K6a: zero logits ----------------
__global__ void k6_zero() {
    int i = blockIdx.x * blockDim.x + threadIdx.x;
    if (i < NB * 64) g_logits[i] = 0.f;
}

// ---------------- K6b: split-K GEMM  logits += Y(256xK) @ W^T(Kx64) ----------------
#define BM 64
#define BK 32
#define KSPLIT 256
__global__ void k6_gemm(const float* __restrict__ w) {
    __shared__ float Ys[BM][BK + 1];
    __shared__ float Ws[64][BK + 1];
    int t = threadIdx.x;                 // 256 threads
    int m0 = blockIdx.x * BM;            // 4 m-tiles
    int kbase = blockIdx.y * KSPLIT;     // 229 k-splits
    int tr = t >> 4;                     // 0..15 (m sub-index)
    int tc = t & 15;                     // 0..15 (n sub-index)
    float acc[4][4] = {};
    for (int kk = 0; kk < KSPLIT; kk += BK) {
#pragma unroll
        for (int r = 0; r < 2; r++) {
            int idx = t + r * 256;             // 0..511 float4 slots
            int row = idx >> 3;                // 0..63
            int kc  = (idx & 7) * 4;
            int kg  = kbase + kk + kc;
            float4 yv = make_float4(0.f, 0.f, 0.f, 0.f);
            float4 wv = make_float4(0.f, 0.f, 0.f, 0.f);
            if (kg < KDIM) {
                yv = *(const float4*)&g_y[(size_t)(m0 + row) * KDIM + kg];
                wv = *(const float4*)&w[(size_t)row * KDIM + kg];
            }
            Ys[row][kc+0] = yv.x; Ys[row][kc+1] = yv.y;
            Ys[row][kc+2] = yv.z; Ys[row][kc+3] = yv.w;
            Ws[row][kc+0] = wv.x; Ws[row][kc+1] = wv.y;
            Ws[row][kc+2] = wv.z; Ws[row][kc+3] = wv.w;
        }
        __syncthreads();
#pragma unroll 8
        for (int k2 = 0; k2 < BK; k2++) {
            float ya[4], wa[4];
#pragma unroll
            for (int u = 0; u < 4; u++) ya[u] = Ys[tr + 16*u][k2];
#pragma unroll
            for (int u = 0; u < 4; u++) wa[u] = Ws[tc + 16*u][k2];
#pragma unroll
            for (int um = 0; um < 4; um++)
#pragma unroll
                for (int un = 0; un < 4; un++)
                    acc[um][un] = fmaf(ya[um], wa[un], acc[um][un]);
        }
        __syncthreads();
    }
#pragma unroll
    for (int um = 0; um < 4; um++)
#pragma unroll
        for (int un = 0; un < 4; un++)
            atomicAdd(&g_logits[(m0 + tr + 16*um) * 64 + (tc + 16*un)], acc[um][un]);
}

// ---------------- K7: bias + softmax(64) ----------------
__global__ void k7_softmax(const float* __restrict__ fb, float* __restrict__ out) {
    int b = blockIdx.x;
    int t = threadIdx.x;   // 64 threads
    float v = g_logits[b * 64 + t] + fb[t];
    __shared__ float r0[2], r1[2];
    float m = v;
#pragma unroll
    for (int o = 16; o; o >>= 1) m = fmaxf(m, __shfl_xor_sync(0xffffffffu, m, o));
    if ((t & 31) == 0) r0[t >> 5] = m;
    __syncthreads();
    m = fmaxf(r0[0], r0[1]);
    float e = expf(v - m);
    float s = e;
#pragma unroll
    for (int o = 16; o; o >>= 1) s += __shfl_xor_sync(0xffffffffu, s, o);
    if ((t & 31) == 0) r1[t >> 5] = s;
    __syncthreads();
    s = r1[0] + r1[1];
    out[b * 64 + t] = e / s;
}

// ---------------- launch ----------------
extern "C" void kernel_launch(void* const* d_in, const int* in_sizes, int n_in,
                              void* d_out, int out_size) {
    const float* verts = (const float*)d_in[0];
    const int*   edges = (const int*)  d_in[1];
    const float* w0a = (const float*)d_in[2];  const float* b0a = (const float*)d_in[3];
    const float* w1a = (const float*)d_in[4];  const float* b1a = (const float*)d_in[5];
    const float* w0b = (const float*)d_in[6];  const float* b0b = (const float*)d_in[7];
    const float* w1b = (const float*)d_in[8];  const float* b1b = (const float*)d_in[9];
    const float* f1w = (const float*)d_in[10]; const float* f1b = (const float*)d_in[11];
    const float* f2w = (const float*)d_in[12]; const float* f2b = (const float*)d_in[13];
    float* out = (float*)d_out;

    k1_pack    <<<(NV + 255) / 256, 256>>>(verts);
    k2_scatter1<<<(NE + 255) / 256, 256>>>(edges);
    k3_lin_a   <<<(NV + 255) / 256, 256>>>(w0a, b0a, w1a, b1a);
    k4_scatter2<<<(NE + 255) / 256, 256>>>(edges);
    k5_fused   <<<(NV + 255) / 256, 256>>>(w0b, b0b, w1b, b1b, f1w, f1b);
    k6_zero    <<<64, 256>>>();
    dim3 g6(256 / BM, (KDIM + KSPLIT - 1) / KSPLIT);   // (4, 229)
    k6_gemm    <<<g6, 256>>>(f2w);
    k7_softmax <<<NB, 64>>>(f2b, out);
}